// round 12
// baseline (speedup 1.0000x reference)
#include <cuda_runtime.h>
#include <cuda_fp16.h>
#include <stdint.h>
#include <math.h>

#define NB 8
#define CDIM 256
#define TDIM 1024
#define OQKV 768

typedef unsigned long long ull;

// Scratch (allocation-free rule: __device__ globals)
__device__ float g_xn[NB * CDIM * TDIM];    //  8 MB
__device__ float g_qkv[NB * OQKV * TDIM];   // 24 MB
__device__ float g_y[NB * CDIM * TDIM];     //  8 MB

__device__ __forceinline__ float ex2(float x) {
    float r; asm("ex2.approx.f32 %0, %1;" : "=f"(r) : "f"(x)); return r;
}
__device__ __forceinline__ uint32_t cvt_tf32(float v) {
    uint32_t o; asm("cvt.rna.tf32.f32 %0, %1;" : "=r"(o) : "f"(v)); return o;
}
__device__ __forceinline__ uint32_t f16x2(float lo, float hi) {
    uint32_t r; asm("cvt.rn.f16x2.f32 %0, %1, %2;" : "=r"(r) : "f"(hi), "f"(lo)); return r;
}
__device__ __forceinline__ uint16_t f16b(float v) {
    uint16_t r; asm("cvt.rn.f16.f32 %0, %1;" : "=h"(r) : "f"(v)); return r;
}
__device__ __forceinline__ uint32_t smem_u32(const void* p) {
    uint32_t a;
    asm("{ .reg .u64 t; cvta.to.shared.u64 t, %1; cvt.u32.u64 %0, t; }"
        : "=r"(a) : "l"(p));
    return a;
}
__device__ __forceinline__ void cp16(uint32_t dst, const void* src) {
    asm volatile("cp.async.cg.shared.global [%0], [%1], 16;" :: "r"(dst), "l"(src));
}
#define CP_COMMIT() asm volatile("cp.async.commit_group;" ::: "memory")
#define CP_WAIT(n)  asm volatile("cp.async.wait_group %0;" :: "n"(n) : "memory")

// mma.sync m16n8k8 tf32, accumulate in place
__device__ __forceinline__ void mma_tf32(float* d, const uint32_t* a, uint32_t b0, uint32_t b1) {
    asm volatile(
        "mma.sync.aligned.m16n8k8.row.col.f32.tf32.tf32.f32 "
        "{%0,%1,%2,%3}, {%4,%5,%6,%7}, {%8,%9}, {%0,%1,%2,%3};"
        : "+f"(d[0]), "+f"(d[1]), "+f"(d[2]), "+f"(d[3])
        : "r"(a[0]), "r"(a[1]), "r"(a[2]), "r"(a[3]), "r"(b0), "r"(b1));
}
// mma.sync m16n8k8 tf32 with zero C
__device__ __forceinline__ void mma_tf32_z(float* d, const uint32_t* a, uint32_t b0, uint32_t b1) {
    asm volatile(
        "mma.sync.aligned.m16n8k8.row.col.f32.tf32.tf32.f32 "
        "{%0,%1,%2,%3}, {%4,%5,%6,%7}, {%8,%9}, {%10,%11,%12,%13};"
        : "=f"(d[0]), "=f"(d[1]), "=f"(d[2]), "=f"(d[3])
        : "r"(a[0]), "r"(a[1]), "r"(a[2]), "r"(a[3]), "r"(b0), "r"(b1),
          "f"(0.f), "f"(0.f), "f"(0.f), "f"(0.f));
}
// mma.sync m16n8k16 f16 inputs, f32 accumulate in place
__device__ __forceinline__ void mma_f16(float* d, const uint32_t* a, uint32_t b0, uint32_t b1) {
    asm volatile(
        "mma.sync.aligned.m16n8k16.row.col.f32.f16.f16.f32 "
        "{%0,%1,%2,%3}, {%4,%5,%6,%7}, {%8,%9}, {%0,%1,%2,%3};"
        : "+f"(d[0]), "+f"(d[1]), "+f"(d[2]), "+f"(d[3])
        : "r"(a[0]), "r"(a[1]), "r"(a[2]), "r"(a[3]), "r"(b0), "r"(b1));
}

// ---------------------------------------------------------------------------
// 1) GroupNorm: one block per (batch, group). 32 ch x 1024 = 32768 elems.
// ---------------------------------------------------------------------------
__global__ void gn_kernel(const float* __restrict__ x,
                          const float* __restrict__ gw,
                          const float* __restrict__ gb) {
    int n = blockIdx.x >> 3;
    int g = blockIdx.x & 7;
    const float4* xb = (const float4*)(x + ((size_t)n * CDIM + g * 32) * TDIM);
    float4* xo = (float4*)(g_xn + ((size_t)n * CDIM + g * 32) * TDIM);
    int tid = threadIdx.x;

    float s = 0.f, ss = 0.f;
    for (int i = tid; i < 8192; i += 256) {
        float4 v = xb[i];
        s  += v.x + v.y + v.z + v.w;
        ss += v.x * v.x + v.y * v.y + v.z * v.z + v.w * v.w;
    }
    __shared__ float rs[8], rss[8];
    #pragma unroll
    for (int off = 16; off > 0; off >>= 1) {
        s  += __shfl_down_sync(0xFFFFFFFFu, s, off);
        ss += __shfl_down_sync(0xFFFFFFFFu, ss, off);
    }
    if ((tid & 31) == 0) { rs[tid >> 5] = s; rss[tid >> 5] = ss; }
    __syncthreads();
    __shared__ float smean, sinv;
    if (tid == 0) {
        float S = 0.f, SS = 0.f;
        #pragma unroll
        for (int i = 0; i < 8; i++) { S += rs[i]; SS += rss[i]; }
        float mean = S * (1.f / 32768.f);
        float var  = SS * (1.f / 32768.f) - mean * mean;
        smean = mean;
        sinv  = rsqrtf(var + 1e-5f);
    }
    __syncthreads();
    float mean = smean, inv = sinv;
    for (int i = tid; i < 8192; i += 256) {
        int c = g * 32 + (i >> 8);
        float w = gw[c] * inv;
        float b = gb[c] - mean * w;
        float4 v = xb[i];
        v.x = v.x * w + b; v.y = v.y * w + b;
        v.z = v.z * w + b; v.w = v.w * w + b;
        xo[i] = v;
    }
}

// ---------------------------------------------------------------------------
// 2,4) cp.async double-buffered warp-MMA tf32 GEMM.
//      Block 128(o) x NTILE(t), K-chunk 32; raw fp32 bits fed to tf32 mma
//      (HW reads 19 bits — truncation, no cvt needed in the stream).
// ---------------------------------------------------------------------------
#define ASTR 36
template <int NTILE, bool RES>
__global__ __launch_bounds__(256, 2)
void gemm_mma(const float* __restrict__ W, const float* __restrict__ X,
              const float* __restrict__ bias, const float* __restrict__ Rp,
              float* __restrict__ out) {
    constexpr int NT = NTILE / 32;          // n-mmas per warp
    constexpr int XSTR = NTILE + 8;
    constexpr int ASZ = 128 * ASTR;         // words per W buffer
    constexpr int XSZ = 32 * XSTR;          // words per X buffer
    extern __shared__ __align__(16) uint32_t dsm[];
    uint32_t* sA[2] = {dsm, dsm + ASZ};
    uint32_t* sX[2] = {dsm + 2 * ASZ, dsm + 2 * ASZ + XSZ};
    uint32_t sbase = smem_u32(dsm);
    uint32_t aoff[2] = {sbase, sbase + ASZ * 4};
    uint32_t xoff[2] = {sbase + 2 * ASZ * 4, sbase + (2 * ASZ + XSZ) * 4};

    int tid = threadIdx.x, wid = tid >> 5, lane = tid & 31;
    int wm = wid & 1, wn = wid >> 1;                  // warp grid 2(m) x 4(n)
    int n = blockIdx.z;
    int o0 = blockIdx.y * 128, t0 = blockIdx.x * NTILE;
    const float* Xb = X + (size_t)n * CDIM * TDIM;

    float acc[4][NT][4];
    #pragma unroll
    for (int i = 0; i < 4; i++)
        #pragma unroll
        for (int j = 0; j < NT; j++)
            #pragma unroll
            for (int c = 0; c < 4; c++) acc[i][j][c] = 0.f;

    auto load_chunk = [&](int k0, int buf) {
        // W chunk: 128 x 32 floats = 1024 float4s
        #pragma unroll
        for (int l = 0; l < 4; l++) {
            int idx = tid + l * 256;
            int r = idx >> 3, c4 = (idx & 7) * 4;
            cp16(aoff[buf] + (r * ASTR + c4) * 4,
                 &W[(size_t)(o0 + r) * CDIM + k0 + c4]);
        }
        // X chunk: 32 x NTILE floats = 8*NT*32 float4s
        #pragma unroll
        for (int l = 0; l < NT; l++) {
            int idx = tid + l * 256;
            int kk = idx / (NTILE / 4), t4 = (idx % (NTILE / 4)) * 4;
            cp16(xoff[buf] + (kk * XSTR + t4) * 4,
                 &Xb[(size_t)(k0 + kk) * TDIM + t0 + t4]);
        }
        CP_COMMIT();
    };

    load_chunk(0, 0);
    #pragma unroll 1
    for (int ch = 0; ch < 8; ch++) {
        int buf = ch & 1;
        if (ch < 7) {
            load_chunk((ch + 1) * 32, buf ^ 1);
            CP_WAIT(1);
        } else {
            CP_WAIT(0);
        }
        __syncthreads();
        #pragma unroll
        for (int ks = 0; ks < 4; ks++) {
            int ar = lane >> 2, ak = lane & 3;
            int bk = lane & 3, bn = lane >> 2;
            uint32_t bf[NT][2];
            #pragma unroll
            for (int nt = 0; nt < NT; nt++) {
                int tcol = wn * (NTILE / 4) + nt * 8 + bn;
                bf[nt][0] = sX[buf][(ks * 8 + bk) * XSTR + tcol];
                bf[nt][1] = sX[buf][(ks * 8 + bk + 4) * XSTR + tcol];
            }
            uint32_t af[4][4];
            #pragma unroll
            for (int mt = 0; mt < 4; mt++) {
                int base = wm * 64 + mt * 16;
                af[mt][0] = sA[buf][(base + ar) * ASTR + ks * 8 + ak];
                af[mt][1] = sA[buf][(base + ar + 8) * ASTR + ks * 8 + ak];
                af[mt][2] = sA[buf][(base + ar) * ASTR + ks * 8 + ak + 4];
                af[mt][3] = sA[buf][(base + ar + 8) * ASTR + ks * 8 + ak + 4];
            }
            #pragma unroll
            for (int mt = 0; mt < 4; mt++)
                #pragma unroll
                for (int nt = 0; nt < NT; nt++)
                    mma_tf32(acc[mt][nt], af[mt], bf[nt][0], bf[nt][1]);
        }
        __syncthreads();
    }

    int row = lane >> 2, colq = (lane & 3) * 2;
    int OROWS = RES ? CDIM : OQKV;
    float* Ob = out + (size_t)n * OROWS * TDIM;
    const float* Rb = RES ? Rp + (size_t)n * OROWS * TDIM : (const float*)0;
    #pragma unroll
    for (int mt = 0; mt < 4; mt++) {
        int or0 = o0 + wm * 64 + mt * 16 + row;
        int or1 = or0 + 8;
        float b0 = bias[or0], b1 = bias[or1];
        #pragma unroll
        for (int nt = 0; nt < NT; nt++) {
            int tc = t0 + wn * (NTILE / 4) + nt * 8 + colq;
            float2 v0, v1;
            v0.x = acc[mt][nt][0] + b0; v0.y = acc[mt][nt][1] + b0;
            v1.x = acc[mt][nt][2] + b1; v1.y = acc[mt][nt][3] + b1;
            size_t off0 = (size_t)or0 * TDIM + tc;
            size_t off1 = (size_t)or1 * TDIM + tc;
            if (RES) {
                float2 r0 = *(const float2*)&Rb[off0];
                float2 r1 = *(const float2*)&Rb[off1];
                v0.x += r0.x; v0.y += r0.y;
                v1.x += r1.x; v1.y += r1.y;
            }
            *(float2*)&Ob[off0] = v0;
            *(float2*)&Ob[off1] = v1;
        }
    }
}

// ---------------------------------------------------------------------------
// 3) Attention, tensor-core flash style (unchanged from R10; ~MUFU floor).
// ---------------------------------------------------------------------------
#define KSTR 1032
#define ATTN_SMEM (8 * KSTR * 4 + 8 * KSTR * 2)
__global__ __launch_bounds__(512)
void attn_mma(const float* __restrict__ qkv, float* __restrict__ y) {
    extern __shared__ __align__(16) float smem[];
    float* sK = smem;                               // [8][KSTR] tf32 bits
    uint16_t* sVT = (uint16_t*)(smem + 8 * KSTR);   // [8][KSTR] fp16 bits
    int h = blockIdx.x, n = blockIdx.y;
    const float* base = qkv + (size_t)n * OQKV * TDIM;
    const float* Qg = base + (size_t)(h * 8) * TDIM;
    const float* Kg = base + (size_t)(CDIM + h * 8) * TDIM;
    const float* Vg = base + (size_t)(2 * CDIM + h * 8) * TDIM;
    int tid = threadIdx.x;

    for (int i = tid; i < 8192; i += 512) {
        int d = i >> 10, t = i & 1023;
        sK[d * KSTR + t]  = __uint_as_float(cvt_tf32(Kg[(size_t)d * TDIM + t]));
        sVT[d * KSTR + t] = f16b(Vg[(size_t)d * TDIM + t]);
    }
    __syncthreads();

    int wid = tid >> 5, lane = tid & 31;
    int r = lane >> 2, cq = lane & 3;
    const float scale2 = 0.35355339059327373f * 1.4426950408889634f; // (1/sqrt(8))*log2(e)

    #pragma unroll
    for (int j = 0; j < 4; j++) {
        int q0 = (wid * 4 + j) * 16;
        uint32_t qa[4];
        qa[0] = cvt_tf32(Qg[(size_t)cq * TDIM + q0 + r] * scale2);
        qa[1] = cvt_tf32(Qg[(size_t)cq * TDIM + q0 + r + 8] * scale2);
        qa[2] = cvt_tf32(Qg[(size_t)(cq + 4) * TDIM + q0 + r] * scale2);
        qa[3] = cvt_tf32(Qg[(size_t)(cq + 4) * TDIM + q0 + r + 8] * scale2);

        float yacc[4] = {0.f, 0.f, 0.f, 0.f};
        float l0 = 0.f, l1 = 0.f;

        #pragma unroll 2
        for (int kt = 0; kt < 64; kt++) {
            int t0 = kt * 16;
            uint32_t kb0a = __float_as_uint(sK[cq * KSTR + t0 + r]);
            uint32_t kb1a = __float_as_uint(sK[(cq + 4) * KSTR + t0 + r]);
            uint32_t kb0b = __float_as_uint(sK[cq * KSTR + t0 + 8 + r]);
            uint32_t kb1b = __float_as_uint(sK[(cq + 4) * KSTR + t0 + 8 + r]);
            float s1[4], s2[4];
            mma_tf32_z(s1, qa, kb0a, kb1a);
            mma_tf32_z(s2, qa, kb0b, kb1b);
            float p10 = ex2(s1[0]), p11 = ex2(s1[1]);
            float p12 = ex2(s1[2]), p13 = ex2(s1[3]);
            float p20 = ex2(s2[0]), p21 = ex2(s2[1]);
            float p22 = ex2(s2[2]), p23 = ex2(s2[3]);
            l0 += (p10 + p11) + (p20 + p21);
            l1 += (p12 + p13) + (p22 + p23);
            uint32_t pa[4];
            pa[0] = f16x2(p10, p11);
            pa[1] = f16x2(p12, p13);
            pa[2] = f16x2(p20, p21);
            pa[3] = f16x2(p22, p23);
            uint32_t vb0 = *(const uint32_t*)&sVT[r * KSTR + t0 + 2 * cq];
            uint32_t vb1 = *(const uint32_t*)&sVT[r * KSTR + t0 + 8 + 2 * cq];
            mma_f16(yacc, pa, vb0, vb1);
        }
        l0 += __shfl_xor_sync(0xFFFFFFFFu, l0, 1);
        l0 += __shfl_xor_sync(0xFFFFFFFFu, l0, 2);
        l1 += __shfl_xor_sync(0xFFFFFFFFu, l1, 1);
        l1 += __shfl_xor_sync(0xFFFFFFFFu, l1, 2);
        float i0 = 1.f / l0, i1 = 1.f / l1;
        float* Yg = y + ((size_t)n * CDIM + h * 8) * TDIM;
        Yg[(size_t)(2 * cq) * TDIM + q0 + r]         = yacc[0] * i0;
        Yg[(size_t)(2 * cq + 1) * TDIM + q0 + r]     = yacc[1] * i0;
        Yg[(size_t)(2 * cq) * TDIM + q0 + r + 8]     = yacc[2] * i1;
        Yg[(size_t)(2 * cq + 1) * TDIM + q0 + r + 8] = yacc[3] * i1;
    }
}

// ---------------------------------------------------------------------------
// Launch
// ---------------------------------------------------------------------------
#define GSMEM(NTILE) ((2 * 128 * ASTR + 2 * 32 * ((NTILE) + 8)) * 4)

extern "C" void kernel_launch(void* const* d_in, const int* in_sizes, int n_in,
                              void* d_out, int out_size) {
    const float* x     = (const float*)d_in[0];
    const float* gn_w  = (const float*)d_in[1];
    const float* gn_b  = (const float*)d_in[2];
    const float* qkv_w = (const float*)d_in[3];
    const float* qkv_b = (const float*)d_in[4];
    const float* out_w = (const float*)d_in[5];
    const float* out_b = (const float*)d_in[6];
    float* out = (float*)d_out;

    float *p_xn, *p_qkv, *p_y;
    cudaGetSymbolAddress((void**)&p_xn,  g_xn);
    cudaGetSymbolAddress((void**)&p_qkv, g_qkv);
    cudaGetSymbolAddress((void**)&p_y,   g_y);

    gn_kernel<<<64, 256>>>(x, gn_w, gn_b);

    cudaFuncSetAttribute(gemm_mma<128, false>,
                         cudaFuncAttributeMaxDynamicSharedMemorySize, GSMEM(128));
    cudaFuncSetAttribute(gemm_mma<64, true>,
                         cudaFuncAttributeMaxDynamicSharedMemorySize, GSMEM(64));

    gemm_mma<128, false><<<dim3(8, 6, 8), 256, GSMEM(128)>>>(qkv_w, p_xn, qkv_b, nullptr, p_qkv);

    cudaFuncSetAttribute(attn_mma, cudaFuncAttributeMaxDynamicSharedMemorySize, ATTN_SMEM);
    attn_mma<<<dim3(32, 8), 512, ATTN_SMEM>>>(p_qkv, p_y);

    gemm_mma<64, true><<<dim3(16, 2, 8), 256, GSMEM(64)>>>(out_w, p_y, out_b, x, out);
}

// round 14
// speedup vs baseline: 1.0518x; 1.0518x over previous
#include <cuda_runtime.h>
#include <cuda_fp16.h>
#include <stdint.h>
#include <math.h>

#define NB 8
#define CDIM 256
#define TDIM 1024
#define OQKV 768
#define W16_OUT_OFF (OQKV * CDIM)

// Scratch (allocation-free rule: __device__ globals). 16B-aligned: these are
// accessed via cp.async-16 / uint4 / uint32_t vector ops.
__device__ __align__(16) uint16_t g_xn16[NB * TDIM * CDIM];     // GN out, fp16 [n][t][c]
__device__ __align__(16) float    g_qkv[NB * OQKV * TDIM];      // fp32 [n][o][t]
__device__ __align__(16) uint16_t g_y16[NB * TDIM * CDIM];      // attn out, fp16 [n][t][c]
__device__ __align__(16) uint16_t g_w16[(OQKV + CDIM) * CDIM];  // fp16 weights (qkv | out)

__device__ __forceinline__ float ex2(float x) {
    float r; asm("ex2.approx.f32 %0, %1;" : "=f"(r) : "f"(x)); return r;
}
__device__ __forceinline__ uint32_t cvt_tf32(float v) {
    uint32_t o; asm("cvt.rna.tf32.f32 %0, %1;" : "=r"(o) : "f"(v)); return o;
}
__device__ __forceinline__ uint32_t f16x2(float lo, float hi) {
    uint32_t r; asm("cvt.rn.f16x2.f32 %0, %1, %2;" : "=r"(r) : "f"(hi), "f"(lo)); return r;
}
__device__ __forceinline__ uint16_t f16b(float v) {
    uint16_t r; asm("cvt.rn.f16.f32 %0, %1;" : "=h"(r) : "f"(v)); return r;
}
__device__ __forceinline__ uint32_t smem_u32(const void* p) {
    uint32_t a;
    asm("{ .reg .u64 t; cvta.to.shared.u64 t, %1; cvt.u32.u64 %0, t; }"
        : "=r"(a) : "l"(p));
    return a;
}
__device__ __forceinline__ void cp16(uint32_t dst, const void* src) {
    asm volatile("cp.async.cg.shared.global [%0], [%1], 16;" :: "r"(dst), "l"(src));
}
#define CP_COMMIT() asm volatile("cp.async.commit_group;" ::: "memory")
#define CP_WAIT(n)  asm volatile("cp.async.wait_group %0;" :: "n"(n) : "memory")

// mma.sync m16n8k8 tf32 with zero C (attention scores)
__device__ __forceinline__ void mma_tf32_z(float* d, const uint32_t* a, uint32_t b0, uint32_t b1) {
    asm volatile(
        "mma.sync.aligned.m16n8k8.row.col.f32.tf32.tf32.f32 "
        "{%0,%1,%2,%3}, {%4,%5,%6,%7}, {%8,%9}, {%10,%11,%12,%13};"
        : "=f"(d[0]), "=f"(d[1]), "=f"(d[2]), "=f"(d[3])
        : "r"(a[0]), "r"(a[1]), "r"(a[2]), "r"(a[3]), "r"(b0), "r"(b1),
          "f"(0.f), "f"(0.f), "f"(0.f), "f"(0.f));
}
// mma.sync m16n8k16 f16 inputs, f32 accumulate in place
__device__ __forceinline__ void mma_f16(float* d, const uint32_t* a, uint32_t b0, uint32_t b1) {
    asm volatile(
        "mma.sync.aligned.m16n8k16.row.col.f32.f16.f16.f32 "
        "{%0,%1,%2,%3}, {%4,%5,%6,%7}, {%8,%9}, {%0,%1,%2,%3};"
        : "+f"(d[0]), "+f"(d[1]), "+f"(d[2]), "+f"(d[3])
        : "r"(a[0]), "r"(a[1]), "r"(a[2]), "r"(a[3]), "r"(b0), "r"(b1));
}

// ---------------------------------------------------------------------------
// 0) Weight conversion fp32 -> fp16 (both matrices, one launch).
// ---------------------------------------------------------------------------
__global__ void conv_w(const float* __restrict__ qkv_w, const float* __restrict__ out_w) {
    const int NQ = OQKV * CDIM / 2;            // u32 pairs
    const int NT = (OQKV + CDIM) * CDIM / 2;
    uint32_t* dst = (uint32_t*)g_w16;
    int gtid = blockIdx.x * 256 + threadIdx.x;
    for (int i = gtid; i < NT; i += 65536) {
        float2 v = (i < NQ) ? ((const float2*)qkv_w)[i]
                            : ((const float2*)out_w)[i - NQ];
        dst[i] = f16x2(v.x, v.y);
    }
}

// ---------------------------------------------------------------------------
// 1) GroupNorm -> fp16 [t][c]. One block per (batch, group).
//    Stats pass on [c][t]; transpose via 64x32 smem tiles, coalesced out.
// ---------------------------------------------------------------------------
__global__ void gn_kernel(const float* __restrict__ x,
                          const float* __restrict__ gw,
                          const float* __restrict__ gb) {
    int n = blockIdx.x >> 3;
    int g = blockIdx.x & 7;
    const float4* xb = (const float4*)(x + ((size_t)n * CDIM + g * 32) * TDIM);
    int tid = threadIdx.x;

    float s = 0.f, ss = 0.f;
    for (int i = tid; i < 8192; i += 256) {
        float4 v = xb[i];
        s  += v.x + v.y + v.z + v.w;
        ss += v.x * v.x + v.y * v.y + v.z * v.z + v.w * v.w;
    }
    __shared__ float rs[8], rss[8];
    #pragma unroll
    for (int off = 16; off > 0; off >>= 1) {
        s  += __shfl_down_sync(0xFFFFFFFFu, s, off);
        ss += __shfl_down_sync(0xFFFFFFFFu, ss, off);
    }
    if ((tid & 31) == 0) { rs[tid >> 5] = s; rss[tid >> 5] = ss; }
    __syncthreads();
    __shared__ float smean, sinv;
    if (tid == 0) {
        float S = 0.f, SS = 0.f;
        #pragma unroll
        for (int i = 0; i < 8; i++) { S += rs[i]; SS += rss[i]; }
        float mean = S * (1.f / 32768.f);
        float var  = SS * (1.f / 32768.f) - mean * mean;
        smean = mean;
        sinv  = rsqrtf(var + 1e-5f);
    }
    __syncthreads();
    __shared__ float swc[32], sbc[32];
    if (tid < 32) {
        float w = gw[g * 32 + tid] * sinv;
        swc[tid] = w;
        sbc[tid] = gb[g * 32 + tid] - smean * w;
    }
    __syncthreads();

    __shared__ __align__(16) uint16_t tb[64][40];
    uint4* dst = (uint4*)(g_xn16 + (size_t)n * TDIM * CDIM);
    for (int tile = 0; tile < 16; tile++) {
        #pragma unroll
        for (int l = 0; l < 2; l++) {
            int idx = tid + l * 256;             // 512 float4s: 32ch x 16 t-quads
            int c = idx >> 4, t16 = idx & 15;
            float4 v = xb[c * 256 + tile * 16 + t16];
            float w = swc[c], b = sbc[c];
            tb[t16 * 4 + 0][c] = f16b(v.x * w + b);
            tb[t16 * 4 + 1][c] = f16b(v.y * w + b);
            tb[t16 * 4 + 2][c] = f16b(v.z * w + b);
            tb[t16 * 4 + 3][c] = f16b(v.w * w + b);
        }
        __syncthreads();
        {   // 64 rows x 4 uint4 (64B per row)
            int row = tid >> 2, seg = tid & 3;
            int t = tile * 64 + row;
            dst[t * 32 + g * 4 + seg] = *(const uint4*)&tb[row][seg * 8];
        }
        __syncthreads();
    }
}

// ---------------------------------------------------------------------------
// 2,4) fp16 warp-MMA GEMM, cp.async double-buffered.
//      Block 128(o) x NTILE(t), K-chunk 32 halves (2x k16 mma steps).
//      W fp16 [o][k]; X fp16 [t][k] (k contiguous = B col-major).
// ---------------------------------------------------------------------------
#define KP 40
template <int NTILE, int OROWS, bool RES>
__global__ __launch_bounds__(256, 2)
void gemm16(const uint16_t* __restrict__ W16, const uint16_t* __restrict__ X16,
            const float* __restrict__ bias, const float* __restrict__ Rp,
            float* __restrict__ out) {
    constexpr int NT = NTILE / 32;            // n-mmas per warp
    constexpr int ASZ = 128 * KP;             // halves per W buffer
    constexpr int XSZ = NTILE * KP;           // halves per X buffer
    extern __shared__ __align__(16) uint16_t hsm[];
    uint16_t* sW[2] = {hsm, hsm + ASZ};
    uint16_t* sX[2] = {hsm + 2 * ASZ, hsm + 2 * ASZ + XSZ};
    uint32_t sbase = smem_u32(hsm);
    uint32_t aoff[2] = {sbase, sbase + ASZ * 2};
    uint32_t xoff[2] = {sbase + 2 * ASZ * 2, sbase + (2 * ASZ + XSZ) * 2};

    int tid = threadIdx.x, wid = tid >> 5, lane = tid & 31;
    int wm = wid & 1, wn = wid >> 1;          // warp grid 2(m) x 4(n)
    int n = blockIdx.z;
    int o0 = blockIdx.y * 128, t0 = blockIdx.x * NTILE;
    const uint16_t* Xb = X16 + (size_t)n * TDIM * CDIM;

    float acc[4][NT][4];
    #pragma unroll
    for (int i = 0; i < 4; i++)
        #pragma unroll
        for (int j = 0; j < NT; j++)
            #pragma unroll
            for (int c = 0; c < 4; c++) acc[i][j][c] = 0.f;

    auto load_chunk = [&](int k0, int buf) {
        // W chunk: 128 rows x 32 halves = 512 cp16
        #pragma unroll
        for (int l = 0; l < 2; l++) {
            int idx = tid + l * 256;
            int r = idx >> 2, seg = idx & 3;
            cp16(aoff[buf] + (r * KP + seg * 8) * 2,
                 &W16[(size_t)(o0 + r) * CDIM + k0 + seg * 8]);
        }
        // X chunk: NTILE rows x 32 halves
        #pragma unroll
        for (int l = 0; l < NTILE / 64; l++) {
            int idx = tid + l * 256;
            int r = idx >> 2, seg = idx & 3;
            cp16(xoff[buf] + (r * KP + seg * 8) * 2,
                 &Xb[(size_t)(t0 + r) * CDIM + k0 + seg * 8]);
        }
        CP_COMMIT();
    };

    load_chunk(0, 0);
    #pragma unroll 1
    for (int ch = 0; ch < 8; ch++) {
        int buf = ch & 1;
        if (ch < 7) {
            load_chunk((ch + 1) * 32, buf ^ 1);
            CP_WAIT(1);
        } else {
            CP_WAIT(0);
        }
        __syncthreads();
        int ar = lane >> 2, c2 = (lane & 3) * 2;
        #pragma unroll
        for (int ks = 0; ks < 2; ks++) {      // two k16 steps
            int kb = ks * 16;
            uint32_t bf[NT][2];
            #pragma unroll
            for (int nt = 0; nt < NT; nt++) {
                int tcol = wn * (NTILE / 4) + nt * 8 + ar;
                bf[nt][0] = *(const uint32_t*)&sX[buf][tcol * KP + kb + c2];
                bf[nt][1] = *(const uint32_t*)&sX[buf][tcol * KP + kb + c2 + 8];
            }
            uint32_t af[4][4];
            #pragma unroll
            for (int mt = 0; mt < 4; mt++) {
                int base = wm * 64 + mt * 16;
                af[mt][0] = *(const uint32_t*)&sW[buf][(base + ar) * KP + kb + c2];
                af[mt][1] = *(const uint32_t*)&sW[buf][(base + ar + 8) * KP + kb + c2];
                af[mt][2] = *(const uint32_t*)&sW[buf][(base + ar) * KP + kb + c2 + 8];
                af[mt][3] = *(const uint32_t*)&sW[buf][(base + ar + 8) * KP + kb + c2 + 8];
            }
            #pragma unroll
            for (int mt = 0; mt < 4; mt++)
                #pragma unroll
                for (int nt = 0; nt < NT; nt++)
                    mma_f16(acc[mt][nt], af[mt], bf[nt][0], bf[nt][1]);
        }
        __syncthreads();
    }

    int row = lane >> 2, colq = (lane & 3) * 2;
    float* Ob = out + (size_t)n * OROWS * TDIM;
    const float* Rb = RES ? Rp + (size_t)n * OROWS * TDIM : (const float*)0;
    #pragma unroll
    for (int mt = 0; mt < 4; mt++) {
        int or0 = o0 + wm * 64 + mt * 16 + row;
        int or1 = or0 + 8;
        float b0 = bias[or0], b1 = bias[or1];
        #pragma unroll
        for (int nt = 0; nt < NT; nt++) {
            int tc = t0 + wn * (NTILE / 4) + nt * 8 + colq;
            float2 v0, v1;
            v0.x = acc[mt][nt][0] + b0; v0.y = acc[mt][nt][1] + b0;
            v1.x = acc[mt][nt][2] + b1; v1.y = acc[mt][nt][3] + b1;
            size_t off0 = (size_t)or0 * TDIM + tc;
            size_t off1 = (size_t)or1 * TDIM + tc;
            if (RES) {
                float2 r0 = *(const float2*)&Rb[off0];
                float2 r1 = *(const float2*)&Rb[off1];
                v0.x += r0.x; v0.y += r0.y;
                v1.x += r1.x; v1.y += r1.y;
            }
            *(float2*)&Ob[off0] = v0;
            *(float2*)&Ob[off1] = v1;
        }
    }
}

// ---------------------------------------------------------------------------
// 3) Attention, tensor-core flash style (math unchanged from R10).
//    Epilogue writes y as fp16 [t][c] pairs for the fp16 out-projection.
// ---------------------------------------------------------------------------
#define KSTR 1032
#define ATTN_SMEM (8 * KSTR * 4 + 8 * KSTR * 2)
__global__ __launch_bounds__(512)
void attn_mma(const float* __restrict__ qkv) {
    extern __shared__ __align__(16) float smem[];
    float* sK = smem;                               // [8][KSTR] tf32 bits
    uint16_t* sVT = (uint16_t*)(smem + 8 * KSTR);   // [8][KSTR] fp16 bits
    int h = blockIdx.x, n = blockIdx.y;
    const float* base = qkv + (size_t)n * OQKV * TDIM;
    const float* Qg = base + (size_t)(h * 8) * TDIM;
    const float* Kg = base + (size_t)(CDIM + h * 8) * TDIM;
    const float* Vg = base + (size_t)(2 * CDIM + h * 8) * TDIM;
    int tid = threadIdx.x;

    for (int i = tid; i < 8192; i += 512) {
        int d = i >> 10, t = i & 1023;
        sK[d * KSTR + t]  = __uint_as_float(cvt_tf32(Kg[(size_t)d * TDIM + t]));
        sVT[d * KSTR + t] = f16b(Vg[(size_t)d * TDIM + t]);
    }
    __syncthreads();

    int wid = tid >> 5, lane = tid & 31;
    int r = lane >> 2, cq = lane & 3;
    const float scale2 = 0.35355339059327373f * 1.4426950408889634f; // (1/sqrt(8))*log2(e)

    #pragma unroll
    for (int j = 0; j < 4; j++) {
        int q0 = (wid * 4 + j) * 16;
        uint32_t qa[4];
        qa[0] = cvt_tf32(Qg[(size_t)cq * TDIM + q0 + r] * scale2);
        qa[1] = cvt_tf32(Qg[(size_t)cq * TDIM + q0 + r + 8] * scale2);
        qa[2] = cvt_tf32(Qg[(size_t)(cq + 4) * TDIM + q0 + r] * scale2);
        qa[3] = cvt_tf32(Qg[(size_t)(cq + 4) * TDIM + q0 + r + 8] * scale2);

        float yacc[4] = {0.f, 0.f, 0.f, 0.f};
        float l0 = 0.f, l1 = 0.f;

        #pragma unroll 2
        for (int kt = 0; kt < 64; kt++) {
            int t0 = kt * 16;
            uint32_t kb0a = __float_as_uint(sK[cq * KSTR + t0 + r]);
            uint32_t kb1a = __float_as_uint(sK[(cq + 4) * KSTR + t0 + r]);
            uint32_t kb0b = __float_as_uint(sK[cq * KSTR + t0 + 8 + r]);
            uint32_t kb1b = __float_as_uint(sK[(cq + 4) * KSTR + t0 + 8 + r]);
            float s1[4], s2[4];
            mma_tf32_z(s1, qa, kb0a, kb1a);
            mma_tf32_z(s2, qa, kb0b, kb1b);
            float p10 = ex2(s1[0]), p11 = ex2(s1[1]);
            float p12 = ex2(s1[2]), p13 = ex2(s1[3]);
            float p20 = ex2(s2[0]), p21 = ex2(s2[1]);
            float p22 = ex2(s2[2]), p23 = ex2(s2[3]);
            l0 += (p10 + p11) + (p20 + p21);
            l1 += (p12 + p13) + (p22 + p23);
            uint32_t pa[4];
            pa[0] = f16x2(p10, p11);
            pa[1] = f16x2(p12, p13);
            pa[2] = f16x2(p20, p21);
            pa[3] = f16x2(p22, p23);
            uint32_t vb0 = *(const uint32_t*)&sVT[r * KSTR + t0 + 2 * cq];
            uint32_t vb1 = *(const uint32_t*)&sVT[r * KSTR + t0 + 8 + 2 * cq];
            mma_f16(yacc, pa, vb0, vb1);
        }
        l0 += __shfl_xor_sync(0xFFFFFFFFu, l0, 1);
        l0 += __shfl_xor_sync(0xFFFFFFFFu, l0, 2);
        l1 += __shfl_xor_sync(0xFFFFFFFFu, l1, 1);
        l1 += __shfl_xor_sync(0xFFFFFFFFu, l1, 2);
        float i0 = 1.f / l0, i1 = 1.f / l1;
        // y fp16 [t][c]: pairs (2cq, 2cq+1) contiguous -> single u32 stores
        uint32_t* Y16 = (uint32_t*)(g_y16 + (size_t)n * TDIM * CDIM);
        Y16[((q0 + r) * CDIM + h * 8 + 2 * cq) >> 1]     = f16x2(yacc[0] * i0, yacc[1] * i0);
        Y16[((q0 + r + 8) * CDIM + h * 8 + 2 * cq) >> 1] = f16x2(yacc[2] * i1, yacc[3] * i1);
    }
}

// ---------------------------------------------------------------------------
// Launch
// ---------------------------------------------------------------------------
#define GSMEM(NTILE) ((2 * 128 * KP + 2 * (NTILE) * KP) * 2)

extern "C" void kernel_launch(void* const* d_in, const int* in_sizes, int n_in,
                              void* d_out, int out_size) {
    const float* x     = (const float*)d_in[0];
    const float* gn_w  = (const float*)d_in[1];
    const float* gn_b  = (const float*)d_in[2];
    const float* qkv_w = (const float*)d_in[3];
    const float* qkv_b = (const float*)d_in[4];
    const float* out_w = (const float*)d_in[5];
    const float* out_b = (const float*)d_in[6];
    float* out = (float*)d_out;

    uint16_t *p_xn16, *p_y16, *p_w16;
    float *p_qkv;
    cudaGetSymbolAddress((void**)&p_xn16, g_xn16);
    cudaGetSymbolAddress((void**)&p_qkv,  g_qkv);
    cudaGetSymbolAddress((void**)&p_y16,  g_y16);
    cudaGetSymbolAddress((void**)&p_w16,  g_w16);

    conv_w<<<256, 256>>>(qkv_w, out_w);
    gn_kernel<<<64, 256>>>(x, gn_w, gn_b);

    cudaFuncSetAttribute(gemm16<128, OQKV, false>,
                         cudaFuncAttributeMaxDynamicSharedMemorySize, GSMEM(128));
    cudaFuncSetAttribute(gemm16<64, CDIM, true>,
                         cudaFuncAttributeMaxDynamicSharedMemorySize, GSMEM(64));

    gemm16<128, OQKV, false><<<dim3(8, 6, 8), 256, GSMEM(128)>>>(
        p_w16, p_xn16, qkv_b, nullptr, p_qkv);

    cudaFuncSetAttribute(attn_mma, cudaFuncAttributeMaxDynamicSharedMemorySize, ATTN_SMEM);
    attn_mma<<<dim3(32, 8), 512, ATTN_SMEM>>>(p_qkv);

    gemm16<64, CDIM, true><<<dim3(16, 2, 8), 256, GSMEM(64)>>>(
        p_w16 + W16_OUT_OFF, p_y16, out_b, x, out);
}

// round 15
// speedup vs baseline: 1.3237x; 1.2585x over previous
#include <cuda_runtime.h>
#include <cuda_fp16.h>
#include <stdint.h>
#include <math.h>

#define NB 8
#define CDIM 256
#define TDIM 1024
#define OQKV 768
#define W16_OUT_OFF (OQKV * CDIM)

// Scratch (allocation-free rule: __device__ globals). 16B-aligned: these are
// accessed via cp.async-16 / uint4 / uint32_t vector ops.
__device__ __align__(16) uint16_t g_xn16[NB * TDIM * CDIM];     // GN out, fp16 [n][t][c]
__device__ __align__(16) float    g_qkv[NB * OQKV * TDIM];      // fp32 [n][o][t]
__device__ __align__(16) uint16_t g_y16[NB * TDIM * CDIM];      // attn out, fp16 [n][t][c]
__device__ __align__(16) uint16_t g_w16[(OQKV + CDIM) * CDIM];  // fp16 weights (qkv | out)

__device__ __forceinline__ uint32_t cvt_tf32(float v) {
    uint32_t o; asm("cvt.rna.tf32.f32 %0, %1;" : "=r"(o) : "f"(v)); return o;
}
__device__ __forceinline__ uint32_t f16x2(float lo, float hi) {
    uint32_t r; asm("cvt.rn.f16x2.f32 %0, %1, %2;" : "=r"(r) : "f"(hi), "f"(lo)); return r;
}
__device__ __forceinline__ uint16_t f16b(float v) {
    uint16_t r; asm("cvt.rn.f16.f32 %0, %1;" : "=h"(r) : "f"(v)); return r;
}
__device__ __forceinline__ uint32_t hex2(uint32_t x) {
    uint32_t r; asm("ex2.approx.f16x2 %0, %1;" : "=r"(r) : "r"(x)); return r;
}
__device__ __forceinline__ uint32_t smem_u32(const void* p) {
    uint32_t a;
    asm("{ .reg .u64 t; cvta.to.shared.u64 t, %1; cvt.u32.u64 %0, t; }"
        : "=r"(a) : "l"(p));
    return a;
}
__device__ __forceinline__ void cp16(uint32_t dst, const void* src) {
    asm volatile("cp.async.cg.shared.global [%0], [%1], 16;" :: "r"(dst), "l"(src));
}
#define CP_COMMIT() asm volatile("cp.async.commit_group;" ::: "memory")
#define CP_WAIT(n)  asm volatile("cp.async.wait_group %0;" :: "n"(n) : "memory")

// mma.sync m16n8k8 f16 scores, f32 accum, C preloaded with softmax shift
#define SSHIFT -6.0f
__device__ __forceinline__ void mma_f16k8_s(float* d, uint32_t a0, uint32_t a1, uint32_t b0) {
    asm volatile(
        "mma.sync.aligned.m16n8k8.row.col.f32.f16.f16.f32 "
        "{%0,%1,%2,%3}, {%4,%5}, {%6}, {%7,%8,%9,%10};"
        : "=f"(d[0]), "=f"(d[1]), "=f"(d[2]), "=f"(d[3])
        : "r"(a0), "r"(a1), "r"(b0),
          "f"(SSHIFT), "f"(SSHIFT), "f"(SSHIFT), "f"(SSHIFT));
}
// mma.sync m16n8k16 f16 inputs, f32 accumulate in place
__device__ __forceinline__ void mma_f16(float* d, const uint32_t* a, uint32_t b0, uint32_t b1) {
    asm volatile(
        "mma.sync.aligned.m16n8k16.row.col.f32.f16.f16.f32 "
        "{%0,%1,%2,%3}, {%4,%5,%6,%7}, {%8,%9}, {%0,%1,%2,%3};"
        : "+f"(d[0]), "+f"(d[1]), "+f"(d[2]), "+f"(d[3])
        : "r"(a[0]), "r"(a[1]), "r"(a[2]), "r"(a[3]), "r"(b0), "r"(b1));
}

// ---------------------------------------------------------------------------
// 0) Weight conversion fp32 -> fp16 (both matrices, one launch).
// ---------------------------------------------------------------------------
__global__ void conv_w(const float* __restrict__ qkv_w, const float* __restrict__ out_w) {
    const int NQ = OQKV * CDIM / 2;            // u32 pairs
    const int NT = (OQKV + CDIM) * CDIM / 2;
    uint32_t* dst = (uint32_t*)g_w16;
    int gtid = blockIdx.x * 256 + threadIdx.x;
    for (int i = gtid; i < NT; i += 65536) {
        float2 v = (i < NQ) ? ((const float2*)qkv_w)[i]
                            : ((const float2*)out_w)[i - NQ];
        dst[i] = f16x2(v.x, v.y);
    }
}

// ---------------------------------------------------------------------------
// 1) GroupNorm -> fp16 [t][c]. One block per (batch, group).
// ---------------------------------------------------------------------------
__global__ void gn_kernel(const float* __restrict__ x,
                          const float* __restrict__ gw,
                          const float* __restrict__ gb) {
    int n = blockIdx.x >> 3;
    int g = blockIdx.x & 7;
    const float4* xb = (const float4*)(x + ((size_t)n * CDIM + g * 32) * TDIM);
    int tid = threadIdx.x;

    float s = 0.f, ss = 0.f;
    for (int i = tid; i < 8192; i += 256) {
        float4 v = xb[i];
        s  += v.x + v.y + v.z + v.w;
        ss += v.x * v.x + v.y * v.y + v.z * v.z + v.w * v.w;
    }
    __shared__ float rs[8], rss[8];
    #pragma unroll
    for (int off = 16; off > 0; off >>= 1) {
        s  += __shfl_down_sync(0xFFFFFFFFu, s, off);
        ss += __shfl_down_sync(0xFFFFFFFFu, ss, off);
    }
    if ((tid & 31) == 0) { rs[tid >> 5] = s; rss[tid >> 5] = ss; }
    __syncthreads();
    __shared__ float smean, sinv;
    if (tid == 0) {
        float S = 0.f, SS = 0.f;
        #pragma unroll
        for (int i = 0; i < 8; i++) { S += rs[i]; SS += rss[i]; }
        float mean = S * (1.f / 32768.f);
        float var  = SS * (1.f / 32768.f) - mean * mean;
        smean = mean;
        sinv  = rsqrtf(var + 1e-5f);
    }
    __syncthreads();
    __shared__ float swc[32], sbc[32];
    if (tid < 32) {
        float w = gw[g * 32 + tid] * sinv;
        swc[tid] = w;
        sbc[tid] = gb[g * 32 + tid] - smean * w;
    }
    __syncthreads();

    __shared__ __align__(16) uint16_t tb[64][40];
    uint4* dst = (uint4*)(g_xn16 + (size_t)n * TDIM * CDIM);
    for (int tile = 0; tile < 16; tile++) {
        #pragma unroll
        for (int l = 0; l < 2; l++) {
            int idx = tid + l * 256;             // 512 float4s: 32ch x 16 t-quads
            int c = idx >> 4, t16 = idx & 15;
            float4 v = xb[c * 256 + tile * 16 + t16];
            float w = swc[c], b = sbc[c];
            tb[t16 * 4 + 0][c] = f16b(v.x * w + b);
            tb[t16 * 4 + 1][c] = f16b(v.y * w + b);
            tb[t16 * 4 + 2][c] = f16b(v.z * w + b);
            tb[t16 * 4 + 3][c] = f16b(v.w * w + b);
        }
        __syncthreads();
        {   // 64 rows x 4 uint4 (64B per row)
            int row = tid >> 2, seg = tid & 3;
            int t = tile * 64 + row;
            dst[t * 32 + g * 4 + seg] = *(const uint4*)&tb[row][seg * 8];
        }
        __syncthreads();
    }
}

// ---------------------------------------------------------------------------
// 2,4) fp16 warp-MMA GEMM, cp.async double-buffered (unchanged from R13).
// ---------------------------------------------------------------------------
#define KP 40
template <int NTILE, int OROWS, bool RES>
__global__ __launch_bounds__(256, 2)
void gemm16(const uint16_t* __restrict__ W16, const uint16_t* __restrict__ X16,
            const float* __restrict__ bias, const float* __restrict__ Rp,
            float* __restrict__ out) {
    constexpr int NT = NTILE / 32;            // n-mmas per warp
    constexpr int ASZ = 128 * KP;             // halves per W buffer
    constexpr int XSZ = NTILE * KP;           // halves per X buffer
    extern __shared__ __align__(16) uint16_t hsm[];
    uint16_t* sW[2] = {hsm, hsm + ASZ};
    uint16_t* sX[2] = {hsm + 2 * ASZ, hsm + 2 * ASZ + XSZ};
    uint32_t sbase = smem_u32(hsm);
    uint32_t aoff[2] = {sbase, sbase + ASZ * 2};
    uint32_t xoff[2] = {sbase + 2 * ASZ * 2, sbase + (2 * ASZ + XSZ) * 2};

    int tid = threadIdx.x, wid = tid >> 5, lane = tid & 31;
    int wm = wid & 1, wn = wid >> 1;          // warp grid 2(m) x 4(n)
    int n = blockIdx.z;
    int o0 = blockIdx.y * 128, t0 = blockIdx.x * NTILE;
    const uint16_t* Xb = X16 + (size_t)n * TDIM * CDIM;

    float acc[4][NT][4];
    #pragma unroll
    for (int i = 0; i < 4; i++)
        #pragma unroll
        for (int j = 0; j < NT; j++)
            #pragma unroll
            for (int c = 0; c < 4; c++) acc[i][j][c] = 0.f;

    auto load_chunk = [&](int k0, int buf) {
        #pragma unroll
        for (int l = 0; l < 2; l++) {
            int idx = tid + l * 256;
            int r = idx >> 2, seg = idx & 3;
            cp16(aoff[buf] + (r * KP + seg * 8) * 2,
                 &W16[(size_t)(o0 + r) * CDIM + k0 + seg * 8]);
        }
        #pragma unroll
        for (int l = 0; l < NTILE / 64; l++) {
            int idx = tid + l * 256;
            int r = idx >> 2, seg = idx & 3;
            cp16(xoff[buf] + (r * KP + seg * 8) * 2,
                 &Xb[(size_t)(t0 + r) * CDIM + k0 + seg * 8]);
        }
        CP_COMMIT();
    };

    load_chunk(0, 0);
    #pragma unroll 1
    for (int ch = 0; ch < 8; ch++) {
        int buf = ch & 1;
        if (ch < 7) {
            load_chunk((ch + 1) * 32, buf ^ 1);
            CP_WAIT(1);
        } else {
            CP_WAIT(0);
        }
        __syncthreads();
        int ar = lane >> 2, c2 = (lane & 3) * 2;
        #pragma unroll
        for (int ks = 0; ks < 2; ks++) {      // two k16 steps
            int kb = ks * 16;
            uint32_t bf[NT][2];
            #pragma unroll
            for (int nt = 0; nt < NT; nt++) {
                int tcol = wn * (NTILE / 4) + nt * 8 + ar;
                bf[nt][0] = *(const uint32_t*)&sX[buf][tcol * KP + kb + c2];
                bf[nt][1] = *(const uint32_t*)&sX[buf][tcol * KP + kb + c2 + 8];
            }
            uint32_t af[4][4];
            #pragma unroll
            for (int mt = 0; mt < 4; mt++) {
                int base = wm * 64 + mt * 16;
                af[mt][0] = *(const uint32_t*)&sW[buf][(base + ar) * KP + kb + c2];
                af[mt][1] = *(const uint32_t*)&sW[buf][(base + ar + 8) * KP + kb + c2];
                af[mt][2] = *(const uint32_t*)&sW[buf][(base + ar) * KP + kb + c2 + 8];
                af[mt][3] = *(const uint32_t*)&sW[buf][(base + ar + 8) * KP + kb + c2 + 8];
            }
            #pragma unroll
            for (int mt = 0; mt < 4; mt++)
                #pragma unroll
                for (int nt = 0; nt < NT; nt++)
                    mma_f16(acc[mt][nt], af[mt], bf[nt][0], bf[nt][1]);
        }
        __syncthreads();
    }

    int row = lane >> 2, colq = (lane & 3) * 2;
    float* Ob = out + (size_t)n * OROWS * TDIM;
    const float* Rb = RES ? Rp + (size_t)n * OROWS * TDIM : (const float*)0;
    #pragma unroll
    for (int mt = 0; mt < 4; mt++) {
        int or0 = o0 + wm * 64 + mt * 16 + row;
        int or1 = or0 + 8;
        float b0 = bias[or0], b1 = bias[or1];
        #pragma unroll
        for (int nt = 0; nt < NT; nt++) {
            int tc = t0 + wn * (NTILE / 4) + nt * 8 + colq;
            float2 v0, v1;
            v0.x = acc[mt][nt][0] + b0; v0.y = acc[mt][nt][1] + b0;
            v1.x = acc[mt][nt][2] + b1; v1.y = acc[mt][nt][3] + b1;
            size_t off0 = (size_t)or0 * TDIM + tc;
            size_t off1 = (size_t)or1 * TDIM + tc;
            if (RES) {
                float2 r0 = *(const float2*)&Rb[off0];
                float2 r1 = *(const float2*)&Rb[off1];
                v0.x += r0.x; v0.y += r0.y;
                v1.x += r1.x; v1.y += r1.y;
            }
            *(float2*)&Ob[off0] = v0;
            *(float2*)&Ob[off1] = v1;
        }
    }
}

// ---------------------------------------------------------------------------
// 3) Attention: all-f16 tensor-core flash. One CTA per (h, n), 512 threads.
//    K fp16 [t][8d]; V fp16 [d][t] (stride KSTR). Per 16-key tile:
//      2x m16n8k8.f16 score mma (C preloaded with -6 shift)
//      4x cvt pack + 4x ex2.approx.f16x2  -> P is directly the f16 A-frag
//      1x PV mma + 1x ones-mma (exact f32 row sums of P = l; no shuffles)
// ---------------------------------------------------------------------------
#define KSTR 1032
__global__ __launch_bounds__(512)
void attn_mma(const float* __restrict__ qkv) {
    __shared__ __align__(16) uint16_t sK16[TDIM * 8];   // [t][d] fp16, 16 KB
    __shared__ __align__(16) uint16_t sV[8 * KSTR];     // [d][t] fp16, 16.1 KB
    int h = blockIdx.x, n = blockIdx.y;
    const float* base = qkv + (size_t)n * OQKV * TDIM;
    const float* Qg = base + (size_t)(h * 8) * TDIM;
    const float* Kg = base + (size_t)(CDIM + h * 8) * TDIM;
    const float* Vg = base + (size_t)(2 * CDIM + h * 8) * TDIM;
    int tid = threadIdx.x;

    for (int i = tid; i < 8192; i += 512) {
        int d = i >> 10, t = i & 1023;
        sK16[t * 8 + d] = f16b(Kg[(size_t)d * TDIM + t]);
        sV[d * KSTR + t] = f16b(Vg[(size_t)d * TDIM + t]);
    }
    __syncthreads();

    int wid = tid >> 5, lane = tid & 31;
    int r = lane >> 2, cq = lane & 3;
    const float scale2 = 0.35355339059327373f * 1.4426950408889634f; // (1/sqrt(8))*log2(e)
    const uint32_t ONES = 0x3C003C00u;   // f16x2 {1.0, 1.0}

    #pragma unroll
    for (int j = 0; j < 4; j++) {
        int q0 = (wid * 4 + j) * 16;
        // f16 A-frag (k8): a0 = Q[q0+r][2cq,2cq+1], a1 = rows +8
        uint32_t qa0 = f16x2(Qg[(size_t)(2 * cq) * TDIM + q0 + r] * scale2,
                             Qg[(size_t)(2 * cq + 1) * TDIM + q0 + r] * scale2);
        uint32_t qa1 = f16x2(Qg[(size_t)(2 * cq) * TDIM + q0 + r + 8] * scale2,
                             Qg[(size_t)(2 * cq + 1) * TDIM + q0 + r + 8] * scale2);

        float yacc[4] = {0.f, 0.f, 0.f, 0.f};
        float lacc[4] = {0.f, 0.f, 0.f, 0.f};

        #pragma unroll 4
        for (int kt = 0; kt < 64; kt++) {
            int t0 = kt * 16;
            // K B-frags (1 reg each): key n-col = t0+r, d pair (2cq, 2cq+1)
            uint32_t kba = *(const uint32_t*)&sK16[(t0 + r) * 8 + 2 * cq];
            uint32_t kbb = *(const uint32_t*)&sK16[(t0 + 8 + r) * 8 + 2 * cq];
            float s1[4], s2[4];
            mma_f16k8_s(s1, qa0, qa1, kba);
            mma_f16k8_s(s2, qa0, qa1, kbb);
            // pack score pairs, exponentiate in f16x2 -> P A-frag directly
            uint32_t pa[4];
            pa[0] = hex2(f16x2(s1[0], s1[1]));   // row r,   keys 2cq,2cq+1
            pa[1] = hex2(f16x2(s1[2], s1[3]));   // row r+8, keys 2cq,2cq+1
            pa[2] = hex2(f16x2(s2[0], s2[1]));   // row r,   keys +8
            pa[3] = hex2(f16x2(s2[2], s2[3]));   // row r+8, keys +8
            uint32_t vb0 = *(const uint32_t*)&sV[r * KSTR + t0 + 2 * cq];
            uint32_t vb1 = *(const uint32_t*)&sV[r * KSTR + t0 + 8 + 2 * cq];
            mma_f16(yacc, pa, vb0, vb1);
            mma_f16(lacc, pa, ONES, ONES);       // exact f32 row sums of P
        }
        float i0 = 1.f / lacc[0];                // full l for row r
        float i1 = 1.f / lacc[2];                // full l for row r+8
        // y fp16 [t][c]: pairs (2cq, 2cq+1) contiguous -> single u32 stores
        uint32_t* Y16 = (uint32_t*)(g_y16 + (size_t)n * TDIM * CDIM);
        Y16[((q0 + r) * CDIM + h * 8 + 2 * cq) >> 1]     = f16x2(yacc[0] * i0, yacc[1] * i0);
        Y16[((q0 + r + 8) * CDIM + h * 8 + 2 * cq) >> 1] = f16x2(yacc[2] * i1, yacc[3] * i1);
    }
}

// ---------------------------------------------------------------------------
// Launch
// ---------------------------------------------------------------------------
#define GSMEM(NTILE) ((2 * 128 * KP + 2 * (NTILE) * KP) * 2)

extern "C" void kernel_launch(void* const* d_in, const int* in_sizes, int n_in,
                              void* d_out, int out_size) {
    const float* x     = (const float*)d_in[0];
    const float* gn_w  = (const float*)d_in[1];
    const float* gn_b  = (const float*)d_in[2];
    const float* qkv_w = (const float*)d_in[3];
    const float* qkv_b = (const float*)d_in[4];
    const float* out_w = (const float*)d_in[5];
    const float* out_b = (const float*)d_in[6];
    float* out = (float*)d_out;

    uint16_t *p_xn16, *p_y16, *p_w16;
    float *p_qkv;
    cudaGetSymbolAddress((void**)&p_xn16, g_xn16);
    cudaGetSymbolAddress((void**)&p_qkv,  g_qkv);
    cudaGetSymbolAddress((void**)&p_y16,  g_y16);
    cudaGetSymbolAddress((void**)&p_w16,  g_w16);

    conv_w<<<256, 256>>>(qkv_w, out_w);
    gn_kernel<<<64, 256>>>(x, gn_w, gn_b);

    cudaFuncSetAttribute(gemm16<128, OQKV, false>,
                         cudaFuncAttributeMaxDynamicSharedMemorySize, GSMEM(128));
    cudaFuncSetAttribute(gemm16<64, CDIM, true>,
                         cudaFuncAttributeMaxDynamicSharedMemorySize, GSMEM(64));

    gemm16<128, OQKV, false><<<dim3(8, 6, 8), 256, GSMEM(128)>>>(
        p_w16, p_xn16, qkv_b, nullptr, p_qkv);

    attn_mma<<<dim3(32, 8), 512>>>(p_qkv);

    gemm16<64, CDIM, true><<<dim3(16, 2, 8), 256, GSMEM(64)>>>(
        p_w16 + W16_OUT_OFF, p_y16, out_b, x, out);
}